// round 13
// baseline (speedup 1.0000x reference)
#include <cuda_runtime.h>
#include <math.h>
#include <stdint.h>

// ---------------- problem constants ----------------
#define DIMC   384
#define HEADS  12
#define HD     32
#define NTOK   256
#define BATCH  256
#define BHH    (BATCH*HEADS)     // 3072
#define MROWS  (BATCH*NTOK)      // 65536
#define EPSF   1e-6f

// ---------------- scratch ----------------
__device__ float g_q[BHH * NTOK * HD];
__device__ float g_k[BHH * NTOK * HD];
__device__ float g_v[BHH * NTOK * HD];
__device__ float g_att[MROWS * DIMC];          // tf32-pre-rounded at attn write
__device__ float g_xr[MROWS * DIMC];           // x pre-rounded
__device__ float g_wqr[3 * DIMC * DIMC];       // qkv_w pre-rounded
__device__ float g_wpr[DIMC * DIMC];           // proj_w pre-rounded

__device__ __forceinline__ uint32_t f2tf32(float x) {
    uint32_t y;
    asm volatile("cvt.rna.tf32.f32 %0, %1;" : "=r"(y) : "f"(x));
    return y;
}

__global__ __launch_bounds__(256) void round_tf32_kernel(
    const float* __restrict__ in, float* __restrict__ out, int n4)
{
    int i = blockIdx.x * 256 + threadIdx.x;
    if (i >= n4) return;
    float4 v = ((const float4*)in)[i];
    v.x = __uint_as_float(f2tf32(v.x));
    v.y = __uint_as_float(f2tf32(v.y));
    v.z = __uint_as_float(f2tf32(v.z));
    v.w = __uint_as_float(f2tf32(v.w));
    ((float4*)out)[i] = v;
}

// ================= tf32 tensor-core GEMM (mma.sync) =================
// out[m][n] = sum_k A[m][k] * W[n][k] (+bias) ; K = 384
// BOTH operands pre-rounded tf32 bits (no cvt in loop).
// 256 threads, BM=BN=128, BK=32, warp tile 64x32 (8 warps, 2x4),
// 2-stage cp.async (72KB -> 2 CTA/SM), explicit frag double-buffer across kk.
#define BM 128
#define BN 128
#define BK 32
#define LDT 36                    // padded stride: conflict-free frag loads
#define TSZ (128*LDT)
#define KTILES (DIMC/BK)          // 12

__device__ __forceinline__ void cp16(uint32_t saddr, const void* g) {
    asm volatile("cp.async.cg.shared.global [%0], [%1], 16;" :: "r"(saddr), "l"(g));
}

__device__ __forceinline__ void mma_tf32(float* d, const uint32_t* a, const uint32_t* b) {
    asm volatile(
        "mma.sync.aligned.m16n8k8.row.col.f32.tf32.tf32.f32 "
        "{%0,%1,%2,%3}, {%4,%5,%6,%7}, {%8,%9}, {%0,%1,%2,%3};"
        : "+f"(d[0]), "+f"(d[1]), "+f"(d[2]), "+f"(d[3])
        : "r"(a[0]), "r"(a[1]), "r"(a[2]), "r"(a[3]), "r"(b[0]), "r"(b[1]));
}

// mode 0: qkv epilogue; mode 1: plain bias into o0
__global__ __launch_bounds__(256, 2) void gemm_tc_kernel(
    const float* __restrict__ A, const float* __restrict__ Bw,
    const float* __restrict__ bias, const float* __restrict__ pos_enc,
    float* __restrict__ o0, int mode)
{
    extern __shared__ uint32_t smem[];          // A[2][TSZ], B[2][TSZ] = 72 KB
    uint32_t* AsBase = smem;
    uint32_t* BsBase = smem + 2 * TSZ;

    const int tid  = threadIdx.x;
    const int lane = tid & 31;
    const int warp = tid >> 5;
    const int wm   = warp >> 2;                 // 0..1 -> M offset 0/64
    const int wn   = warp & 3;                  // 0..3 -> N offset 0/32/64/96
    const int m0   = blockIdx.y * BM;
    const int n0   = blockIdx.x * BN;
    const int m0w  = wm * 64;
    const int n0w  = wn * 32;
    const int r    = lane >> 2;                 // 0..7
    const int cth  = lane & 3;                  // 0..3

    const uint32_t sA0 = (uint32_t)__cvta_generic_to_shared(AsBase);
    const uint32_t sB0 = (uint32_t)__cvta_generic_to_shared(BsBase);

    float acc[4][4][4];                         // 64 regs
#pragma unroll
    for (int mt = 0; mt < 4; mt++)
#pragma unroll
        for (int nt = 0; nt < 4; nt++)
#pragma unroll
            for (int q = 0; q < 4; q++) acc[mt][nt][q] = 0.f;

    auto issue_tile = [&](int t, int s) {
#pragma unroll
        for (int i = 0; i < 4; i++) {
            int idx = tid + i * 256;
            int row = idx >> 3;
            int c4  = (idx & 7) << 2;
            cp16(sA0 + ((s * TSZ + row * LDT + c4) << 2),
                 A + (size_t)(m0 + row) * DIMC + t * BK + c4);
            cp16(sB0 + ((s * TSZ + row * LDT + c4) << 2),
                 Bw + (size_t)(n0 + row) * DIMC + t * BK + c4);
        }
        asm volatile("cp.async.commit_group;");
    };

    issue_tile(0, 0);

    for (int t = 0; t < KTILES; t++) {
        if (t + 1 < KTILES) {
            issue_tile(t + 1, (t + 1) & 1);
            asm volatile("cp.async.wait_group 1;");
        } else {
            asm volatile("cp.async.wait_group 0;");
        }
        __syncthreads();

        const uint32_t* Asu = AsBase + (t & 1) * TSZ;
        const uint32_t* Bsu = BsBase + (t & 1) * TSZ;

        // fragment double-buffer across kk
        uint32_t af[2][4][4], bf[2][4][2];
        auto load_frags = [&](int buf, int kk) {
#pragma unroll
            for (int mt = 0; mt < 4; mt++) {
                const uint32_t* ap = Asu + (m0w + mt * 16 + r) * LDT + kk + cth;
                af[buf][mt][0] = ap[0];
                af[buf][mt][1] = ap[8 * LDT];
                af[buf][mt][2] = ap[4];
                af[buf][mt][3] = ap[8 * LDT + 4];
            }
#pragma unroll
            for (int nt = 0; nt < 4; nt++) {
                const uint32_t* bp = Bsu + (n0w + nt * 8 + r) * LDT + kk + cth;
                bf[buf][nt][0] = bp[0];
                bf[buf][nt][1] = bp[4];
            }
        };

        load_frags(0, 0);
#pragma unroll
        for (int kks = 0; kks < 4; kks++) {
            const int cur = kks & 1;
            if (kks < 3) load_frags(cur ^ 1, (kks + 1) * 8);
#pragma unroll
            for (int mt = 0; mt < 4; mt++)
#pragma unroll
                for (int nt = 0; nt < 4; nt++)
                    mma_tf32(acc[mt][nt], af[cur][mt], bf[cur][nt]);
        }
        __syncthreads();
    }

    // ---------------- epilogue ----------------
    if (mode == 1) {
#pragma unroll
        for (int mt = 0; mt < 4; mt++) {
            int mr = m0 + m0w + mt * 16 + r;
#pragma unroll
            for (int nt = 0; nt < 4; nt++) {
                int cb = n0 + n0w + nt * 8 + cth * 2;
                float2 bv = *(const float2*)(bias + cb);
                float2 v0 = make_float2(acc[mt][nt][0] + bv.x, acc[mt][nt][1] + bv.y);
                float2 v1 = make_float2(acc[mt][nt][2] + bv.x, acc[mt][nt][3] + bv.y);
                *(float2*)(o0 + (size_t)mr * DIMC + cb)       = v0;
                *(float2*)(o0 + (size_t)(mr + 8) * DIMC + cb) = v1;
            }
        }
    } else {
        const int part = n0 / DIMC;
#pragma unroll
        for (int mt = 0; mt < 4; mt++) {
#pragma unroll
            for (int rr = 0; rr < 2; rr++) {
                int mr = m0 + m0w + mt * 16 + r + rr * 8;
                int b  = mr >> 8;
                int n  = mr & 255;
#pragma unroll
                for (int nt = 0; nt < 4; nt++) {
                    int col = n0 + n0w + nt * 8 + cth * 2;
                    int cc  = col - part * DIMC;
                    int h   = cc >> 5;
                    int c   = cc & 31;
                    float2 bv = *(const float2*)(bias + col);
                    float v0 = acc[mt][nt][rr * 2 + 0] + bv.x;
                    float v1 = acc[mt][nt][rr * 2 + 1] + bv.y;
                    size_t idx = ((size_t)(b * HEADS + h) * NTOK + n) * HD + c;
                    if (part == 0) {
                        *(float2*)(g_q + idx) = make_float2(fmaxf(v0, 0.f), fmaxf(v1, 0.f));
                    } else if (part == 1) {
                        float2 pv = *(const float2*)(pos_enc + (size_t)n * DIMC + cc);
                        *(float2*)(g_k + idx) =
                            make_float2(fmaxf(v0 + pv.x, 0.f), fmaxf(v1 + pv.y, 0.f));
                    } else {
                        *(float2*)(g_v + idx) = make_float2(v0, v1);
                    }
                }
            }
        }
    }
}

// ---------------- per-head linear attention + depthwise conv (R12 version) ----------------
#define KVP_LD 36
#define SMEM_ATTN_FLOATS (256*36*2 + 4*32*KVP_LD + 256 + 32 + 800 + 32)

__global__ __launch_bounds__(256, 2) void attn_kernel(
    const float* __restrict__ dwc_w, const float* __restrict__ dwc_b)
{
    extern __shared__ float sm[];
    float* ks    = sm;                      // [256][36] (k; later att staging)
    float* vs    = ks + 256 * 36;           // [256][36]
    float* kvp   = vs + 256 * 36;           // [4][32][KVP_LD]
    float* ksump = kvp + 4 * 32 * KVP_LD;   // [8][32]
    float* ksum  = ksump + 256;             // [32]
    float* wc    = ksum + 32;               // [32][25]
    float* bc    = wc + 800;                // [32]

    const int head = blockIdx.x;
    const int tid  = threadIdx.x;
    const size_t base = (size_t)head * NTOK * HD;

#pragma unroll
    for (int it = 0; it < 8; it++) {
        int idx4 = tid + it * 256;
        int j    = idx4 >> 3;
        int c4   = (idx4 & 7) << 2;
        *(float4*)&ks[j * 36 + c4] = *(const float4*)(g_k + base + (size_t)idx4 * 4);
        *(float4*)&vs[j * 36 + c4] = *(const float4*)(g_v + base + (size_t)idx4 * 4);
    }
    for (int i = tid; i < 800; i += 256) wc[i] = dwc_w[i];
    if (tid < 32) bc[tid] = dwc_b[tid];
    __syncthreads();

    {
        int c = tid & 31, g = tid >> 5;
        float s = 0.f;
#pragma unroll 8
        for (int jj = 0; jj < 32; jj++) s += ks[(g * 32 + jj) * 36 + c];
        ksump[g * 32 + c] = s;
    }
    {
        const int jg = tid >> 6;
        const int rm = tid & 63;
        const int c0 = (rm >> 3) * 4;
        const int d0 = (rm & 7) * 4;
        float a[4][4];
#pragma unroll
        for (int ci = 0; ci < 4; ci++)
#pragma unroll
            for (int dj = 0; dj < 4; dj++) a[ci][dj] = 0.f;
        const int jbase = jg * 64;
#pragma unroll 4
        for (int jj = 0; jj < 64; jj++) {
            int j = jbase + jj;
            float4 k4 = *(const float4*)(ks + j * 36 + c0);
            float4 v4 = *(const float4*)(vs + j * 36 + d0);
            a[0][0] = fmaf(k4.x, v4.x, a[0][0]); a[0][1] = fmaf(k4.x, v4.y, a[0][1]);
            a[0][2] = fmaf(k4.x, v4.z, a[0][2]); a[0][3] = fmaf(k4.x, v4.w, a[0][3]);
            a[1][0] = fmaf(k4.y, v4.x, a[1][0]); a[1][1] = fmaf(k4.y, v4.y, a[1][1]);
            a[1][2] = fmaf(k4.y, v4.z, a[1][2]); a[1][3] = fmaf(k4.y, v4.w, a[1][3]);
            a[2][0] = fmaf(k4.z, v4.x, a[2][0]); a[2][1] = fmaf(k4.z, v4.y, a[2][1]);
            a[2][2] = fmaf(k4.z, v4.z, a[2][2]); a[2][3] = fmaf(k4.z, v4.w, a[2][3]);
            a[3][0] = fmaf(k4.w, v4.x, a[3][0]); a[3][1] = fmaf(k4.w, v4.y, a[3][1]);
            a[3][2] = fmaf(k4.w, v4.z, a[3][2]); a[3][3] = fmaf(k4.w, v4.w, a[3][3]);
        }
        float* pb = kvp + jg * 32 * KVP_LD;
#pragma unroll
        for (int ci = 0; ci < 4; ci++)
            *(float4*)(pb + (c0 + ci) * KVP_LD + d0) =
                make_float4(a[ci][0], a[ci][1], a[ci][2], a[ci][3]);
    }
    __syncthreads();

    if (tid < 32) {
        float s = 0.f;
#pragma unroll
        for (int g = 0; g < 8; g++) s += ksump[g * 32 + tid];
        ksum[tid] = s;
    }
    {
        int c  = tid >> 3;
        int d0 = (tid & 7) * 4;
        int off = c * KVP_LD + d0;
        float4 s0 = *(const float4*)(kvp + off);
        float4 s1 = *(const float4*)(kvp + 32 * KVP_LD + off);
        float4 s2 = *(const float4*)(kvp + 64 * KVP_LD + off);
        float4 s3 = *(const float4*)(kvp + 96 * KVP_LD + off);
        s0.x += s1.x + s2.x + s3.x;
        s0.y += s1.y + s2.y + s3.y;
        s0.z += s1.z + s2.z + s3.z;
        s0.w += s1.w + s2.w + s3.w;
        *(float4*)(kvp + off) = s0;
    }
    __syncthreads();

    {
        const int i = tid;
        float q[HD];
#pragma unroll
        for (int t = 0; t < 8; t++) {
            float4 q4 = *(const float4*)(g_q + base + (size_t)i * HD + t * 4);
            q[t * 4 + 0] = q4.x; q[t * 4 + 1] = q4.y;
            q[t * 4 + 2] = q4.z; q[t * 4 + 3] = q4.w;
        }
        float zden = EPSF;
#pragma unroll
        for (int c = 0; c < HD; c++) zden = fmaf(q[c], ksum[c], zden);
        float z = 1.f / zden;

        float out[HD];
#pragma unroll
        for (int d = 0; d < HD; d++) out[d] = 0.f;
#pragma unroll
        for (int c = 0; c < HD; c++) {
            float qc = q[c];
            const float* kr = kvp + c * KVP_LD;
#pragma unroll
            for (int d4 = 0; d4 < HD; d4 += 4) {
                float4 k4 = *(const float4*)(kr + d4);
                out[d4 + 0] = fmaf(qc, k4.x, out[d4 + 0]);
                out[d4 + 1] = fmaf(qc, k4.y, out[d4 + 1]);
                out[d4 + 2] = fmaf(qc, k4.z, out[d4 + 2]);
                out[d4 + 3] = fmaf(qc, k4.w, out[d4 + 3]);
            }
        }
#pragma unroll
        for (int t = 0; t < 8; t++)
            *(float4*)(ks + i * 36 + t * 4) =
                make_float4(out[t*4+0]*z, out[t*4+1]*z, out[t*4+2]*z, out[t*4+3]*z);
    }
    __syncthreads();

    {
        const int dg = tid & 7;
        const int tg = tid >> 3;
        const int d0 = dg * 4;
        const int y  = tg >> 1;
        const int x0 = (tg & 1) * 8;

        float acc[8][4];
#pragma unroll
        for (int xi = 0; xi < 8; xi++)
#pragma unroll
            for (int dd = 0; dd < 4; dd++) acc[xi][dd] = 0.f;

#pragma unroll
        for (int dy = -2; dy <= 2; dy++) {
            int yy = y + dy;
            if (yy < 0 || yy > 15) continue;
            float w[5][4];
#pragma unroll
            for (int dxi = 0; dxi < 5; dxi++)
#pragma unroll
                for (int dd = 0; dd < 4; dd++)
                    w[dxi][dd] = wc[(d0 + dd) * 25 + (dy + 2) * 5 + dxi];
#pragma unroll
            for (int xo = -2; xo <= 9; xo++) {
                int xx = x0 + xo;
                if (xx < 0 || xx > 15) continue;
                float4 v4 = *(const float4*)(vs + (yy * 16 + xx) * 36 + d0);
#pragma unroll
                for (int dxi = 0; dxi < 5; dxi++) {
                    int xi = xo - (dxi - 2);
                    if (xi < 0 || xi > 7) continue;
                    acc[xi][0] = fmaf(v4.x, w[dxi][0], acc[xi][0]);
                    acc[xi][1] = fmaf(v4.y, w[dxi][1], acc[xi][1]);
                    acc[xi][2] = fmaf(v4.z, w[dxi][2], acc[xi][2]);
                    acc[xi][3] = fmaf(v4.w, w[dxi][3], acc[xi][3]);
                }
            }
        }

        const int b = head / HEADS, h = head % HEADS;
#pragma unroll
        for (int xi = 0; xi < 8; xi++) {
            int n = y * 16 + x0 + xi;
            const float* as = ks + n * 36 + d0;
            float4 r;    // pre-round to tf32 (bit-identical to proj in-loop cvt)
            r.x = __uint_as_float(f2tf32(as[0] + acc[xi][0] + bc[d0 + 0]));
            r.y = __uint_as_float(f2tf32(as[1] + acc[xi][1] + bc[d0 + 1]));
            r.z = __uint_as_float(f2tf32(as[2] + acc[xi][2] + bc[d0 + 2]));
            r.w = __uint_as_float(f2tf32(as[3] + acc[xi][3] + bc[d0 + 3]));
            *(float4*)(g_att + ((size_t)(b * NTOK + n)) * DIMC + h * HD + d0) = r;
        }
    }
}

// ---------------- launch ----------------
extern "C" void kernel_launch(void* const* d_in, const int* in_sizes, int n_in,
                              void* d_out, int out_size)
{
    const float* x      = (const float*)d_in[0];
    const float* qkv_w  = (const float*)d_in[1];
    const float* qkv_b  = (const float*)d_in[2];
    const float* pos    = (const float*)d_in[3];
    const float* dwc_w  = (const float*)d_in[4];
    const float* dwc_b  = (const float*)d_in[5];
    const float* proj_w = (const float*)d_in[6];
    const float* proj_b = (const float*)d_in[7];
    float* out = (float*)d_out;

    const int smem_gemm = 4 * TSZ * (int)sizeof(uint32_t);          // 73,728 B
    const int smem_attn = SMEM_ATTN_FLOATS * (int)sizeof(float);

    static float *att_ptr = nullptr, *xr_ptr = nullptr, *wq_ptr = nullptr, *wp_ptr = nullptr;
    if (att_ptr == nullptr) {
        cudaGetSymbolAddress((void**)&att_ptr, g_att);
        cudaGetSymbolAddress((void**)&xr_ptr,  g_xr);
        cudaGetSymbolAddress((void**)&wq_ptr,  g_wqr);
        cudaGetSymbolAddress((void**)&wp_ptr,  g_wpr);
        cudaFuncSetAttribute(gemm_tc_kernel,
                             cudaFuncAttributeMaxDynamicSharedMemorySize, smem_gemm);
        cudaFuncSetAttribute(attn_kernel,
                             cudaFuncAttributeMaxDynamicSharedMemorySize, smem_attn);
    }

    // 0) pre-round all GEMM operands (bit-identical to in-loop cvt)
    {
        int n4x = MROWS * DIMC / 4;
        round_tf32_kernel<<<(n4x + 255) / 256, 256>>>(x, xr_ptr, n4x);
        int n4q = 3 * DIMC * DIMC / 4;
        round_tf32_kernel<<<(n4q + 255) / 256, 256>>>(qkv_w, wq_ptr, n4q);
        int n4p = DIMC * DIMC / 4;
        round_tf32_kernel<<<(n4p + 255) / 256, 256>>>(proj_w, wp_ptr, n4p);
    }

    // 1) qkv GEMM -> relu/pos -> g_q,g_k,g_v head-major
    dim3 g1(3 * DIMC / BN, MROWS / BM);   // (9, 512)
    gemm_tc_kernel<<<g1, 256, smem_gemm>>>(xr_ptr, wq_ptr, qkv_b, pos, nullptr, 0);

    // 2) linear attention + depthwise conv -> g_att (tf32-rounded)
    attn_kernel<<<BHH, 256, smem_attn>>>(dwc_w, dwc_b);

    // 3) proj GEMM -> out
    dim3 g3(DIMC / BN, MROWS / BM);       // (3, 512)
    gemm_tc_kernel<<<g3, 256, smem_gemm>>>(att_ptr, wp_ptr, proj_b, nullptr, out, 1);
}

// round 16
// speedup vs baseline: 2.0327x; 2.0327x over previous
#include <cuda_runtime.h>
#include <cuda_fp16.h>
#include <math.h>
#include <stdint.h>

// ---------------- problem constants ----------------
#define DIMC   384
#define HEADS  12
#define HD     32
#define NTOK   256
#define BATCH  256
#define BHH    (BATCH*HEADS)     // 3072
#define MROWS  (BATCH*NTOK)      // 65536
#define EPSF   1e-6f

// ---------------- scratch ----------------
__device__ float  g_q[BHH * NTOK * HD];
__device__ float  g_k[BHH * NTOK * HD];
__device__ float  g_v[BHH * NTOK * HD];
__device__ __half g_att[MROWS * DIMC];          // attn writes fp16 directly
__device__ __half g_xh[MROWS * DIMC];           // x -> fp16
__device__ __half g_wqh[3 * DIMC * DIMC];       // qkv_w -> fp16
__device__ __half g_wph[DIMC * DIMC];           // proj_w -> fp16

// ---------------- fp32 -> fp16 convert (rn) ----------------
__global__ __launch_bounds__(256) void to_half_kernel(
    const float* __restrict__ in, __half* __restrict__ out, int n4)
{
    int i = blockIdx.x * 256 + threadIdx.x;
    if (i >= n4) return;
    float4 v = ((const float4*)in)[i];
    __half2 h0 = __floats2half2_rn(v.x, v.y);
    __half2 h1 = __floats2half2_rn(v.z, v.w);
    ((__half2*)out)[i * 2 + 0] = h0;
    ((__half2*)out)[i * 2 + 1] = h1;
}

// ================= fp16 tensor-core GEMM (mma.sync m16n8k16) =================
// out[m][n] = sum_k A[m][k] * W[n][k] (+bias), K=384, A/W fp16, acc fp32.
// 256 threads, BM=BN=128, BK=32 halves, warp tile 64x32 (8 warps, 2x4),
// 2-stage cp.async (R7-proven structure).
#define BM 128
#define BN 128
#define BKH 32                    // halves per K-tile
#define LDTH 20                   // words/row: 16 data + 4 pad; (20r+c)%32 bijective
#define TSZH (128*LDTH)           // words per stage per operand
#define KTILES (DIMC/BKH)         // 12

__device__ __forceinline__ void cp16(uint32_t saddr, const void* g) {
    asm volatile("cp.async.cg.shared.global [%0], [%1], 16;" :: "r"(saddr), "l"(g));
}

__device__ __forceinline__ void mma_f16(float* d, const uint32_t* a, const uint32_t* b) {
    asm volatile(
        "mma.sync.aligned.m16n8k16.row.col.f32.f16.f16.f32 "
        "{%0,%1,%2,%3}, {%4,%5,%6,%7}, {%8,%9}, {%0,%1,%2,%3};"
        : "+f"(d[0]), "+f"(d[1]), "+f"(d[2]), "+f"(d[3])
        : "r"(a[0]), "r"(a[1]), "r"(a[2]), "r"(a[3]), "r"(b[0]), "r"(b[1]));
}

// mode 0: qkv epilogue (relu / pos_enc / scatter head-major); mode 1: bias into o0
__global__ __launch_bounds__(256, 2) void gemm_h_kernel(
    const __half* __restrict__ A, const __half* __restrict__ Bw,
    const float* __restrict__ bias, const float* __restrict__ pos_enc,
    float* __restrict__ o0, int mode)
{
    extern __shared__ uint32_t smem[];          // A[2][TSZH], B[2][TSZH] = 40 KB
    uint32_t* AsBase = smem;
    uint32_t* BsBase = smem + 2 * TSZH;

    const int tid  = threadIdx.x;
    const int lane = tid & 31;
    const int warp = tid >> 5;
    const int wm   = warp >> 2;                 // 0..1 -> M offset 0/64
    const int wn   = warp & 3;                  // 0..3 -> N offset 0/32/64/96
    const int m0   = blockIdx.y * BM;
    const int n0   = blockIdx.x * BN;
    const int m0w  = wm * 64;
    const int n0w  = wn * 32;
    const int r    = lane >> 2;                 // 0..7
    const int cth  = lane & 3;                  // 0..3

    const uint32_t sA0 = (uint32_t)__cvta_generic_to_shared(AsBase);
    const uint32_t sB0 = (uint32_t)__cvta_generic_to_shared(BsBase);

    float acc[4][4][4];                         // 64 regs
#pragma unroll
    for (int mt = 0; mt < 4; mt++)
#pragma unroll
        for (int nt = 0; nt < 4; nt++)
#pragma unroll
            for (int q = 0; q < 4; q++) acc[mt][nt][q] = 0.f;

    // per tile: 128 rows x 64B = 512 x 16B per operand; 256 threads -> 2 chunks each
    auto issue_tile = [&](int t, int s) {
#pragma unroll
        for (int i = 0; i < 2; i++) {
            int idx = tid + i * 256;            // 0..511
            int row = idx >> 2;                 // 0..127
            int ch  = idx & 3;                  // 16B chunk = 8 halves
            cp16(sA0 + ((s * TSZH + row * LDTH + ch * 4) << 2),
                 A + (size_t)(m0 + row) * DIMC + t * BKH + ch * 8);
            cp16(sB0 + ((s * TSZH + row * LDTH + ch * 4) << 2),
                 Bw + (size_t)(n0 + row) * DIMC + t * BKH + ch * 8);
        }
        asm volatile("cp.async.commit_group;");
    };

    issue_tile(0, 0);

    for (int t = 0; t < KTILES; t++) {
        if (t + 1 < KTILES) {
            issue_tile(t + 1, (t + 1) & 1);
            asm volatile("cp.async.wait_group 1;");
        } else {
            asm volatile("cp.async.wait_group 0;");
        }
        __syncthreads();

        const uint32_t* Asu = AsBase + (t & 1) * TSZH;
        const uint32_t* Bsu = BsBase + (t & 1) * TSZH;

#pragma unroll
        for (int kw = 0; kw < 16; kw += 8) {    // 2 k16-steps per tile
            uint32_t af[4][4], bf[4][2];
#pragma unroll
            for (int mt = 0; mt < 4; mt++) {
                const uint32_t* ap = Asu + (m0w + mt * 16 + r) * LDTH + kw + cth;
                af[mt][0] = ap[0];              // (r,      k=2c..2c+1)
                af[mt][1] = ap[8 * LDTH];       // (r+8,    k=2c..2c+1)
                af[mt][2] = ap[4];              // (r,      k=2c+8..9)
                af[mt][3] = ap[8 * LDTH + 4];   // (r+8,    k=2c+8..9)
            }
#pragma unroll
            for (int nt = 0; nt < 4; nt++) {
                const uint32_t* bp = Bsu + (n0w + nt * 8 + r) * LDTH + kw + cth;
                bf[nt][0] = bp[0];              // (n=r, k=2c..2c+1)
                bf[nt][1] = bp[4];              // (n=r, k=2c+8..9)
            }
#pragma unroll
            for (int mt = 0; mt < 4; mt++)
#pragma unroll
                for (int nt = 0; nt < 4; nt++)
                    mma_f16(acc[mt][nt], af[mt], bf[nt]);
        }
        __syncthreads();
    }

    // ---------------- epilogue (fp32) ----------------
    // element map: d0@(mr,cb), d1@(mr,cb+1), d2@(mr+8,cb), d3@(mr+8,cb+1)
    if (mode == 1) {
#pragma unroll
        for (int mt = 0; mt < 4; mt++) {
            int mr = m0 + m0w + mt * 16 + r;
#pragma unroll
            for (int nt = 0; nt < 4; nt++) {
                int cb = n0 + n0w + nt * 8 + cth * 2;
                float2 bv = *(const float2*)(bias + cb);
                float2 v0 = make_float2(acc[mt][nt][0] + bv.x, acc[mt][nt][1] + bv.y);
                float2 v1 = make_float2(acc[mt][nt][2] + bv.x, acc[mt][nt][3] + bv.y);
                *(float2*)(o0 + (size_t)mr * DIMC + cb)       = v0;
                *(float2*)(o0 + (size_t)(mr + 8) * DIMC + cb) = v1;
            }
        }
    } else {
        const int part = n0 / DIMC;             // BN=128 divides q/k/v boundaries
#pragma unroll
        for (int mt = 0; mt < 4; mt++) {
#pragma unroll
            for (int rr = 0; rr < 2; rr++) {
                int mr = m0 + m0w + mt * 16 + r + rr * 8;
                int b  = mr >> 8;
                int n  = mr & 255;
#pragma unroll
                for (int nt = 0; nt < 4; nt++) {
                    int col = n0 + n0w + nt * 8 + cth * 2;
                    int cc  = col - part * DIMC;
                    int h   = cc >> 5;
                    int c   = cc & 31;
                    float2 bv = *(const float2*)(bias + col);
                    float v0 = acc[mt][nt][rr * 2 + 0] + bv.x;
                    float v1 = acc[mt][nt][rr * 2 + 1] + bv.y;
                    size_t idx = ((size_t)(b * HEADS + h) * NTOK + n) * HD + c;
                    if (part == 0) {
                        *(float2*)(g_q + idx) = make_float2(fmaxf(v0, 0.f), fmaxf(v1, 0.f));
                    } else if (part == 1) {
                        float2 pv = *(const float2*)(pos_enc + (size_t)n * DIMC + cc);
                        *(float2*)(g_k + idx) =
                            make_float2(fmaxf(v0 + pv.x, 0.f), fmaxf(v1 + pv.y, 0.f));
                    } else {
                        *(float2*)(g_v + idx) = make_float2(v0, v1);
                    }
                }
            }
        }
    }
}

// ---------------- per-head linear attention + depthwise conv (R12, half output) ----------------
#define KVP_LD 36
#define SMEM_ATTN_FLOATS (256*36*2 + 4*32*KVP_LD + 256 + 32 + 800 + 32)

__global__ __launch_bounds__(256, 2) void attn_kernel(
    const float* __restrict__ dwc_w, const float* __restrict__ dwc_b)
{
    extern __shared__ float sm[];
    float* ks    = sm;                      // [256][36] (k; later att staging)
    float* vs    = ks + 256 * 36;           // [256][36]
    float* kvp   = vs + 256 * 36;           // [4][32][KVP_LD]
    float* ksump = kvp + 4 * 32 * KVP_LD;   // [8][32]
    float* ksum  = ksump + 256;             // [32]
    float* wc    = ksum + 32;               // [32][25]
    float* bc    = wc + 800;                // [32]

    const int head = blockIdx.x;
    const int tid  = threadIdx.x;
    const size_t base = (size_t)head * NTOK * HD;

#pragma unroll
    for (int it = 0; it < 8; it++) {
        int idx4 = tid + it * 256;
        int j    = idx4 >> 3;
        int c4   = (idx4 & 7) << 2;
        *(float4*)&ks[j * 36 + c4] = *(const float4*)(g_k + base + (size_t)idx4 * 4);
        *(float4*)&vs[j * 36 + c4] = *(const float4*)(g_v + base + (size_t)idx4 * 4);
    }
    for (int i = tid; i < 800; i += 256) wc[i] = dwc_w[i];
    if (tid < 32) bc[tid] = dwc_b[tid];
    __syncthreads();

    {
        int c = tid & 31, g = tid >> 5;
        float s = 0.f;
#pragma unroll 8
        for (int jj = 0; jj < 32; jj++) s += ks[(g * 32 + jj) * 36 + c];
        ksump[g * 32 + c] = s;
    }
    {
        const int jg = tid >> 6;
        const int rm = tid & 63;
        const int c0 = (rm >> 3) * 4;
        const int d0 = (rm & 7) * 4;
        float a[4][4];
#pragma unroll
        for (int ci = 0; ci < 4; ci++)
#pragma unroll
            for (int dj = 0; dj < 4; dj++) a[ci][dj] = 0.f;
        const int jbase = jg * 64;
#pragma unroll 4
        for (int jj = 0; jj < 64; jj++) {
            int j = jbase + jj;
            float4 k4 = *(const float4*)(ks + j * 36 + c0);
            float4 v4 = *(const float4*)(vs + j * 36 + d0);
            a[0][0] = fmaf(k4.x, v4.x, a[0][0]); a[0][1] = fmaf(k4.x, v4.y, a[0][1]);
            a[0][2] = fmaf(k4.x, v4.z, a[0][2]); a[0][3] = fmaf(k4.x, v4.w, a[0][3]);
            a[1][0] = fmaf(k4.y, v4.x, a[1][0]); a[1][1] = fmaf(k4.y, v4.y, a[1][1]);
            a[1][2] = fmaf(k4.y, v4.z, a[1][2]); a[1][3] = fmaf(k4.y, v4.w, a[1][3]);
            a[2][0] = fmaf(k4.z, v4.x, a[2][0]); a[2][1] = fmaf(k4.z, v4.y, a[2][1]);
            a[2][2] = fmaf(k4.z, v4.z, a[2][2]); a[2][3] = fmaf(k4.z, v4.w, a[2][3]);
            a[3][0] = fmaf(k4.w, v4.x, a[3][0]); a[3][1] = fmaf(k4.w, v4.y, a[3][1]);
            a[3][2] = fmaf(k4.w, v4.z, a[3][2]); a[3][3] = fmaf(k4.w, v4.w, a[3][3]);
        }
        float* pb = kvp + jg * 32 * KVP_LD;
#pragma unroll
        for (int ci = 0; ci < 4; ci++)
            *(float4*)(pb + (c0 + ci) * KVP_LD + d0) =
                make_float4(a[ci][0], a[ci][1], a[ci][2], a[ci][3]);
    }
    __syncthreads();

    if (tid < 32) {
        float s = 0.f;
#pragma unroll
        for (int g = 0; g < 8; g++) s += ksump[g * 32 + tid];
        ksum[tid] = s;
    }
    {
        int c  = tid >> 3;
        int d0 = (tid & 7) * 4;
        int off = c * KVP_LD + d0;
        float4 s0 = *(const float4*)(kvp + off);
        float4 s1 = *(const float4*)(kvp + 32 * KVP_LD + off);
        float4 s2 = *(const float4*)(kvp + 64 * KVP_LD + off);
        float4 s3 = *(const float4*)(kvp + 96 * KVP_LD + off);
        s0.x += s1.x + s2.x + s3.x;
        s0.y += s1.y + s2.y + s3.y;
        s0.z += s1.z + s2.z + s3.z;
        s0.w += s1.w + s2.w + s3.w;
        *(float4*)(kvp + off) = s0;
    }
    __syncthreads();

    {
        const int i = tid;
        float q[HD];
#pragma unroll
        for (int t = 0; t < 8; t++) {
            float4 q4 = *(const float4*)(g_q + base + (size_t)i * HD + t * 4);
            q[t * 4 + 0] = q4.x; q[t * 4 + 1] = q4.y;
            q[t * 4 + 2] = q4.z; q[t * 4 + 3] = q4.w;
        }
        float zden = EPSF;
#pragma unroll
        for (int c = 0; c < HD; c++) zden = fmaf(q[c], ksum[c], zden);
        float z = 1.f / zden;

        float out[HD];
#pragma unroll
        for (int d = 0; d < HD; d++) out[d] = 0.f;
#pragma unroll
        for (int c = 0; c < HD; c++) {
            float qc = q[c];
            const float* kr = kvp + c * KVP_LD;
#pragma unroll
            for (int d4 = 0; d4 < HD; d4 += 4) {
                float4 k4 = *(const float4*)(kr + d4);
                out[d4 + 0] = fmaf(qc, k4.x, out[d4 + 0]);
                out[d4 + 1] = fmaf(qc, k4.y, out[d4 + 1]);
                out[d4 + 2] = fmaf(qc, k4.z, out[d4 + 2]);
                out[d4 + 3] = fmaf(qc, k4.w, out[d4 + 3]);
            }
        }
#pragma unroll
        for (int t = 0; t < 8; t++)
            *(float4*)(ks + i * 36 + t * 4) =
                make_float4(out[t*4+0]*z, out[t*4+1]*z, out[t*4+2]*z, out[t*4+3]*z);
    }
    __syncthreads();

    {
        const int dg = tid & 7;
        const int tg = tid >> 3;
        const int d0 = dg * 4;
        const int y  = tg >> 1;
        const int x0 = (tg & 1) * 8;

        float acc[8][4];
#pragma unroll
        for (int xi = 0; xi < 8; xi++)
#pragma unroll
            for (int dd = 0; dd < 4; dd++) acc[xi][dd] = 0.f;

#pragma unroll
        for (int dy = -2; dy <= 2; dy++) {
            int yy = y + dy;
            if (yy < 0 || yy > 15) continue;
            float w[5][4];
#pragma unroll
            for (int dxi = 0; dxi < 5; dxi++)
#pragma unroll
                for (int dd = 0; dd < 4; dd++)
                    w[dxi][dd] = wc[(d0 + dd) * 25 + (dy + 2) * 5 + dxi];
#pragma unroll
            for (int xo = -2; xo <= 9; xo++) {
                int xx = x0 + xo;
                if (xx < 0 || xx > 15) continue;
                float4 v4 = *(const float4*)(vs + (yy * 16 + xx) * 36 + d0);
#pragma unroll
                for (int dxi = 0; dxi < 5; dxi++) {
                    int xi = xo - (dxi - 2);
                    if (xi < 0 || xi > 7) continue;
                    acc[xi][0] = fmaf(v4.x, w[dxi][0], acc[xi][0]);
                    acc[xi][1] = fmaf(v4.y, w[dxi][1], acc[xi][1]);
                    acc[xi][2] = fmaf(v4.z, w[dxi][2], acc[xi][2]);
                    acc[xi][3] = fmaf(v4.w, w[dxi][3], acc[xi][3]);
                }
            }
        }

        const int b = head / HEADS, h = head % HEADS;
#pragma unroll
        for (int xi = 0; xi < 8; xi++) {
            int n = y * 16 + x0 + xi;
            const float* as = ks + n * 36 + d0;
            __half2 h0 = __floats2half2_rn(as[0] + acc[xi][0] + bc[d0 + 0],
                                           as[1] + acc[xi][1] + bc[d0 + 1]);
            __half2 h1 = __floats2half2_rn(as[2] + acc[xi][2] + bc[d0 + 2],
                                           as[3] + acc[xi][3] + bc[d0 + 3]);
            __half2* dst = (__half2*)(g_att + ((size_t)(b * NTOK + n)) * DIMC + h * HD + d0);
            dst[0] = h0;
            dst[1] = h1;
        }
    }
}

// ---------------- launch ----------------
extern "C" void kernel_launch(void* const* d_in, const int* in_sizes, int n_in,
                              void* d_out, int out_size)
{
    const float* x      = (const float*)d_in[0];
    const float* qkv_w  = (const float*)d_in[1];
    const float* qkv_b  = (const float*)d_in[2];
    const float* pos    = (const float*)d_in[3];
    const float* dwc_w  = (const float*)d_in[4];
    const float* dwc_b  = (const float*)d_in[5];
    const float* proj_w = (const float*)d_in[6];
    const float* proj_b = (const float*)d_in[7];
    float* out = (float*)d_out;

    const int smem_gemm = 4 * TSZH * (int)sizeof(uint32_t);   // 40,960 B
    const int smem_attn = SMEM_ATTN_FLOATS * (int)sizeof(float);

    static __half *att_ptr = nullptr, *xh_ptr = nullptr, *wq_ptr = nullptr, *wp_ptr = nullptr;
    if (att_ptr == nullptr) {
        cudaGetSymbolAddress((void**)&att_ptr, g_att);
        cudaGetSymbolAddress((void**)&xh_ptr,  g_xh);
        cudaGetSymbolAddress((void**)&wq_ptr,  g_wqh);
        cudaGetSymbolAddress((void**)&wp_ptr,  g_wph);
        cudaFuncSetAttribute(gemm_h_kernel,
                             cudaFuncAttributeMaxDynamicSharedMemorySize, smem_gemm);
        cudaFuncSetAttribute(attn_kernel,
                             cudaFuncAttributeMaxDynamicSharedMemorySize, smem_attn);
    }

    // 0) convert GEMM operands to fp16 (rn)
    {
        int n4x = MROWS * DIMC / 4;
        to_half_kernel<<<(n4x + 255) / 256, 256>>>(x, xh_ptr, n4x);
        int n4q = 3 * DIMC * DIMC / 4;
        to_half_kernel<<<(n4q + 255) / 256, 256>>>(qkv_w, wq_ptr, n4q);
        int n4p = DIMC * DIMC / 4;
        to_half_kernel<<<(n4p + 255) / 256, 256>>>(proj_w, wp_ptr, n4p);
    }

    // 1) qkv GEMM (fp16 mma) -> relu/pos -> g_q,g_k,g_v head-major (fp32)
    dim3 g1(3 * DIMC / BN, MROWS / BM);   // (9, 512)
    gemm_h_kernel<<<g1, 256, smem_gemm>>>(xh_ptr, wq_ptr, qkv_b, pos, nullptr, 0);

    // 2) linear attention + depthwise conv -> g_att (fp16)
    attn_kernel<<<BHH, 256, smem_attn>>>(dwc_w, dwc_b);

    // 3) proj GEMM (fp16 mma) -> out (fp32)
    dim3 g3(DIMC / BN, MROWS / BM);       // (3, 512)
    gemm_h_kernel<<<g3, 256, smem_gemm>>>(att_ptr, wp_ptr, proj_b, nullptr, out, 1);
}